// round 1
// baseline (speedup 1.0000x reference)
#include <cuda_runtime.h>

#define B_   4
#define S_   2048
#define D_   1024
#define H_   16
#define DH_  64
#define BH_  (B_*H_)

// Scratch (allocation-free rule: __device__ globals)
__device__ float g_q[(size_t)BH_ * S_ * DH_];     // [b,h,s,d] 32MB
__device__ float g_k[(size_t)BH_ * S_ * DH_];     // [b,h,s,d] 32MB
__device__ float g_ksum[BH_ * DH_];               // sum over s of k

// ---------------------------------------------------------------------------
// Kernel 1: fused q/k projection.  C[m,n] = sum_k x[m,k]*W[n,k] + b[n]
// m = b*S + s  (M=8192), n = (h*64 + d)*2 + c  (N=2048), K=1024.
// Scatter epilogue writes q (c==0) / k (c==1) into [b,h,s,d] layout.
// ---------------------------------------------------------------------------
__global__ __launch_bounds__(256) void proj_kernel(const float* __restrict__ x,
                                                   const float* __restrict__ W,
                                                   const float* __restrict__ bias) {
    const int BK = 16;
    __shared__ float As[64][BK + 1];   // [m][k], odd-ish stride 17 -> <=2-way conflicts
    __shared__ float Bs[64][BK + 1];   // [n][k]

    const int tid = threadIdx.x;
    const int tx = tid & 15, ty = tid >> 4;
    const int bm = blockIdx.y, bn = blockIdx.x;

    const float* Ab = x + (size_t)bm * 64 * D_;
    const float* Bb = W + (size_t)bn * 64 * D_;

    const int lr = tid >> 2;         // 0..63  row within tile
    const int lc = (tid & 3) << 2;   // 0,4,8,12 col within BK

    float acc[4][4] = {};

    for (int k0 = 0; k0 < D_; k0 += BK) {
        float4 a = *(const float4*)(Ab + (size_t)lr * D_ + k0 + lc);
        float4 b = *(const float4*)(Bb + (size_t)lr * D_ + k0 + lc);
        As[lr][lc + 0] = a.x; As[lr][lc + 1] = a.y; As[lr][lc + 2] = a.z; As[lr][lc + 3] = a.w;
        Bs[lr][lc + 0] = b.x; Bs[lr][lc + 1] = b.y; Bs[lr][lc + 2] = b.z; Bs[lr][lc + 3] = b.w;
        __syncthreads();
#pragma unroll
        for (int k = 0; k < BK; k++) {
            float ar[4], br[4];
#pragma unroll
            for (int i = 0; i < 4; i++) ar[i] = As[ty * 4 + i][k];   // broadcast across tx
#pragma unroll
            for (int j = 0; j < 4; j++) br[j] = Bs[tx * 4 + j][k];   // ~2-way
#pragma unroll
            for (int i = 0; i < 4; i++)
#pragma unroll
                for (int j = 0; j < 4; j++)
                    acc[i][j] += ar[i] * br[j];
        }
        __syncthreads();
    }

    // epilogue: scatter into q/k [b,h,s,d]
#pragma unroll
    for (int i = 0; i < 4; i++) {
        int mm = bm * 64 + ty * 4 + i;
        int bb = mm >> 11;          // / 2048
        int ss = mm & 2047;
#pragma unroll
        for (int j = 0; j < 4; j++) {
            int n = bn * 64 + tx * 4 + j;
            float v = acc[i][j] + bias[n];
            int hd = n >> 1;
            int h  = hd >> 6;
            int d  = hd & 63;
            size_t off = (((size_t)(bb * H_ + h) * S_) + ss) * DH_ + d;
            if ((n & 1) == 0) g_q[off] = v;
            else              g_k[off] = v;
        }
    }
}

// ---------------------------------------------------------------------------
// Kernel 2: ksum[b,h,d] = sum_s k[b,h,s,d]   (enables O(S) row-mean)
// ---------------------------------------------------------------------------
__global__ void ksum_kernel() {
    int bh = blockIdx.x;
    int d = threadIdx.x;  // 64 threads
    const float* kp = g_k + (size_t)bh * S_ * DH_ + d;
    float s0 = 0.f, s1 = 0.f, s2 = 0.f, s3 = 0.f;
    for (int j = 0; j < S_; j += 4) {
        s0 += kp[(size_t)(j + 0) * DH_];
        s1 += kp[(size_t)(j + 1) * DH_];
        s2 += kp[(size_t)(j + 2) * DH_];
        s3 += kp[(size_t)(j + 3) * DH_];
    }
    g_ksum[bh * DH_ + d] = (s0 + s1) + (s2 + s3);
}

// ---------------------------------------------------------------------------
// Kernel 3: fused attention.  Per (b,h, 64-row i-tile):
//   mean[i] = scale/S * q_i . ksum
//   loop j-tiles: P = selu(Q K^T * scale - mean); O += P V;  V read from x.
//   out[b,s,h*64+d] = O * S^-0.5
// ---------------------------------------------------------------------------
#define ATTN_SMEM_FLOATS (64*64 + 64*65 + 64*64 + 64*65 + 64 + 64)
#define ATTN_SMEM_BYTES  (ATTN_SMEM_FLOATS * 4)

__global__ __launch_bounds__(256) void attn_kernel(const float* __restrict__ x,
                                                   float* __restrict__ out) {
    extern __shared__ float smem[];
    float* Qs    = smem;                 // [64][64]  stride 64 (broadcast reads)
    float* Ks    = Qs + 64 * 64;         // [64][65]  odd stride (tx-varying row reads)
    float* Vs    = Ks + 64 * 65;         // [64][64]
    float* Ps    = Vs + 64 * 64;         // [64][65]
    float* ksumS = Ps + 64 * 65;         // [64]
    float* meanS = ksumS + 64;           // [64]

    const int tid = threadIdx.x;
    const int tx = tid & 15, ty = tid >> 4;
    const int bh = blockIdx.y;
    const int b = bh >> 4, h = bh & 15;
    const int i0 = blockIdx.x * 64;

    const float* qb = g_q + ((size_t)bh * S_ + i0) * DH_;
    const float* kb = g_k + (size_t)bh * S_ * DH_;
    const float* vb = x + (size_t)b * S_ * D_ + h * DH_;

    // load Q tile (natural layout)
    {
        int r = tid >> 4;          // 0..15
        int c = (tid & 15) * 4;    // 0..60
#pragma unroll
        for (int rr = 0; rr < 4; rr++) {
            int row = r + rr * 16;
            float4 v = *(const float4*)(qb + (size_t)row * DH_ + c);
            Qs[row * 64 + c + 0] = v.x; Qs[row * 64 + c + 1] = v.y;
            Qs[row * 64 + c + 2] = v.z; Qs[row * 64 + c + 3] = v.w;
        }
    }
    if (tid < 64) ksumS[tid] = g_ksum[bh * DH_ + tid];
    __syncthreads();

    if (tid < 64) {
        float m = 0.f;
#pragma unroll 8
        for (int d = 0; d < DH_; d++) {
            int dd = (d + tid) & 63;                  // skew: avoid 32-way conflicts
            m += Qs[tid * 64 + dd] * ksumS[dd];
        }
        meanS[tid] = m * (0.125f / 2048.0f);          // scale/S
    }
    __syncthreads();

    float o[4][4] = {};
    const float lam = 1.0507009873554805f;
    const float la  = 1.0507009873554805f * 1.6732632423543772f;

    for (int j0 = 0; j0 < S_; j0 += 64) {
        // load K tile ([j][d], stride 65) and V tile ([j][d], stride 64)
        {
            int r = tid >> 4;
            int c = (tid & 15) * 4;
#pragma unroll
            for (int rr = 0; rr < 4; rr++) {
                int row = r + rr * 16;
                float4 kv = *(const float4*)(kb + (size_t)(j0 + row) * DH_ + c);
                Ks[row * 65 + c + 0] = kv.x; Ks[row * 65 + c + 1] = kv.y;
                Ks[row * 65 + c + 2] = kv.z; Ks[row * 65 + c + 3] = kv.w;
                float4 vv = *(const float4*)(vb + (size_t)(j0 + row) * D_ + c);
                Vs[row * 64 + c + 0] = vv.x; Vs[row * 64 + c + 1] = vv.y;
                Vs[row * 64 + c + 2] = vv.z; Vs[row * 64 + c + 3] = vv.w;
            }
        }
        __syncthreads();

        // GEMM1: sacc[i][j] = sum_d Q[i,d] * K[j,d]
        float sacc[4][4] = {};
#pragma unroll 8
        for (int d = 0; d < DH_; d++) {
            float ar[4], br[4];
#pragma unroll
            for (int i = 0; i < 4; i++) ar[i] = Qs[(ty * 4 + i) * 64 + d];
#pragma unroll
            for (int j = 0; j < 4; j++) br[j] = Ks[(tx * 4 + j) * 65 + d];
#pragma unroll
            for (int i = 0; i < 4; i++)
#pragma unroll
                for (int j = 0; j < 4; j++)
                    sacc[i][j] += ar[i] * br[j];
        }

        // selu(sim*scale - mean) -> P
#pragma unroll
        for (int i = 0; i < 4; i++) {
            float mn = meanS[ty * 4 + i];
#pragma unroll
            for (int j = 0; j < 4; j++) {
                float v = sacc[i][j] * 0.125f - mn;
                float p = (v > 0.f) ? lam * v : la * (__expf(v) - 1.f);
                Ps[(ty * 4 + i) * 65 + tx * 4 + j] = p;
            }
        }
        __syncthreads();

        // GEMM2: o[i][d] += sum_j P[i,j] * V[j,d]
#pragma unroll 8
        for (int j = 0; j < 64; j++) {
            float ar[4];
#pragma unroll
            for (int i = 0; i < 4; i++) ar[i] = Ps[(ty * 4 + i) * 65 + j];  // broadcast
            float4 bv = *(const float4*)&Vs[j * 64 + tx * 4];
            float br[4] = {bv.x, bv.y, bv.z, bv.w};
#pragma unroll
            for (int i = 0; i < 4; i++)
#pragma unroll
                for (int d = 0; d < 4; d++)
                    o[i][d] += ar[i] * br[d];
        }
        __syncthreads();
    }

    // epilogue: out[b, s, h*64 + d], scaled by S^-0.5
    const float invS = 0.02209708691207961f;  // 2048^-0.5
#pragma unroll
    for (int i = 0; i < 4; i++) {
        int s = i0 + ty * 4 + i;
        float* op = out + ((size_t)b * S_ + s) * D_ + h * DH_ + tx * 4;
#pragma unroll
        for (int d = 0; d < 4; d++) op[d] = o[i][d] * invS;
    }
}

// ---------------------------------------------------------------------------
extern "C" void kernel_launch(void* const* d_in, const int* in_sizes, int n_in,
                              void* d_out, int out_size) {
    const float* x = (const float*)d_in[0];
    const float* W = (const float*)d_in[1];
    const float* b = (const float*)d_in[2];
    float* out = (float*)d_out;

    cudaFuncSetAttribute(attn_kernel, cudaFuncAttributeMaxDynamicSharedMemorySize,
                         ATTN_SMEM_BYTES);

    proj_kernel<<<dim3(32, 128), 256>>>(x, W, b);
    ksum_kernel<<<BH_, DH_>>>();
    attn_kernel<<<dim3(S_ / 64, BH_), 256, ATTN_SMEM_BYTES>>>(x, out);
}

// round 2
// speedup vs baseline: 1.0013x; 1.0013x over previous
#include <cuda_runtime.h>

#define B_   4
#define S_   2048
#define D_   1024
#define H_   16
#define DH_  64
#define BH_  (B_*H_)

// Scratch (allocation-free rule: __device__ globals)
__device__ float g_q[(size_t)BH_ * S_ * DH_];     // [b,h,s,d] 32MB
__device__ float g_k[(size_t)BH_ * S_ * DH_];     // [b,h,s,d] 32MB
__device__ float g_ksum[BH_ * DH_];               // sum over s of k

// ---------------------------------------------------------------------------
// Kernel 1: fused q/k projection.  C[m,n] = sum_k x[m,k]*W[n,k] + b[n]
// m = b*S + s  (M=8192), n = (h*64 + d)*2 + c  (N=2048), K=1024.
// Scatter epilogue writes q (c==0) / k (c==1) into [b,h,s,d] layout.
// ---------------------------------------------------------------------------
__global__ __launch_bounds__(256) void proj_kernel(const float* __restrict__ x,
                                                   const float* __restrict__ W,
                                                   const float* __restrict__ bias) {
    const int BK = 16;
    __shared__ float As[64][BK + 1];   // [m][k], odd-ish stride 17 -> <=2-way conflicts
    __shared__ float Bs[64][BK + 1];   // [n][k]

    const int tid = threadIdx.x;
    const int tx = tid & 15, ty = tid >> 4;
    const int bm = blockIdx.y, bn = blockIdx.x;

    const float* Ab = x + (size_t)bm * 64 * D_;
    const float* Bb = W + (size_t)bn * 64 * D_;

    const int lr = tid >> 2;         // 0..63  row within tile
    const int lc = (tid & 3) << 2;   // 0,4,8,12 col within BK

    float acc[4][4] = {};

    for (int k0 = 0; k0 < D_; k0 += BK) {
        float4 a = *(const float4*)(Ab + (size_t)lr * D_ + k0 + lc);
        float4 b = *(const float4*)(Bb + (size_t)lr * D_ + k0 + lc);
        As[lr][lc + 0] = a.x; As[lr][lc + 1] = a.y; As[lr][lc + 2] = a.z; As[lr][lc + 3] = a.w;
        Bs[lr][lc + 0] = b.x; Bs[lr][lc + 1] = b.y; Bs[lr][lc + 2] = b.z; Bs[lr][lc + 3] = b.w;
        __syncthreads();
#pragma unroll
        for (int k = 0; k < BK; k++) {
            float ar[4], br[4];
#pragma unroll
            for (int i = 0; i < 4; i++) ar[i] = As[ty * 4 + i][k];   // broadcast across tx
#pragma unroll
            for (int j = 0; j < 4; j++) br[j] = Bs[tx * 4 + j][k];   // ~2-way
#pragma unroll
            for (int i = 0; i < 4; i++)
#pragma unroll
                for (int j = 0; j < 4; j++)
                    acc[i][j] += ar[i] * br[j];
        }
        __syncthreads();
    }

    // epilogue: scatter into q/k [b,h,s,d]
#pragma unroll
    for (int i = 0; i < 4; i++) {
        int mm = bm * 64 + ty * 4 + i;
        int bb = mm >> 11;          // / 2048
        int ss = mm & 2047;
#pragma unroll
        for (int j = 0; j < 4; j++) {
            int n = bn * 64 + tx * 4 + j;
            float v = acc[i][j] + bias[n];
            int hd = n >> 1;
            int h  = hd >> 6;
            int d  = hd & 63;
            size_t off = (((size_t)(bb * H_ + h) * S_) + ss) * DH_ + d;
            if ((n & 1) == 0) g_q[off] = v;
            else              g_k[off] = v;
        }
    }
}

// ---------------------------------------------------------------------------
// Kernel 2: ksum[b,h,d] = sum_s k[b,h,s,d]   (enables O(S) row-mean)
// ---------------------------------------------------------------------------
__global__ void ksum_kernel() {
    int bh = blockIdx.x;
    int d = threadIdx.x;  // 64 threads
    const float* kp = g_k + (size_t)bh * S_ * DH_ + d;
    float s0 = 0.f, s1 = 0.f, s2 = 0.f, s3 = 0.f;
    for (int j = 0; j < S_; j += 4) {
        s0 += kp[(size_t)(j + 0) * DH_];
        s1 += kp[(size_t)(j + 1) * DH_];
        s2 += kp[(size_t)(j + 2) * DH_];
        s3 += kp[(size_t)(j + 3) * DH_];
    }
    g_ksum[bh * DH_ + d] = (s0 + s1) + (s2 + s3);
}

// ---------------------------------------------------------------------------
// Kernel 3: fused attention.  Per (b,h, 64-row i-tile):
//   mean[i] = scale/S * q_i . ksum
//   loop j-tiles: P = selu(Q K^T * scale - mean); O += P V;  V read from x.
//   out[b,s,h*64+d] = O * S^-0.5
// ---------------------------------------------------------------------------
#define ATTN_SMEM_FLOATS (64*64 + 64*65 + 64*64 + 64*65 + 64 + 64)
#define ATTN_SMEM_BYTES  (ATTN_SMEM_FLOATS * 4)

__global__ __launch_bounds__(256) void attn_kernel(const float* __restrict__ x,
                                                   float* __restrict__ out) {
    extern __shared__ float smem[];
    float* Qs    = smem;                 // [64][64]  stride 64 (broadcast reads)
    float* Ks    = Qs + 64 * 64;         // [64][65]  odd stride (tx-varying row reads)
    float* Vs    = Ks + 64 * 65;         // [64][64]
    float* Ps    = Vs + 64 * 64;         // [64][65]
    float* ksumS = Ps + 64 * 65;         // [64]
    float* meanS = ksumS + 64;           // [64]

    const int tid = threadIdx.x;
    const int tx = tid & 15, ty = tid >> 4;
    const int bh = blockIdx.y;
    const int b = bh >> 4, h = bh & 15;
    const int i0 = blockIdx.x * 64;

    const float* qb = g_q + ((size_t)bh * S_ + i0) * DH_;
    const float* kb = g_k + (size_t)bh * S_ * DH_;
    const float* vb = x + (size_t)b * S_ * D_ + h * DH_;

    // load Q tile (natural layout)
    {
        int r = tid >> 4;          // 0..15
        int c = (tid & 15) * 4;    // 0..60
#pragma unroll
        for (int rr = 0; rr < 4; rr++) {
            int row = r + rr * 16;
            float4 v = *(const float4*)(qb + (size_t)row * DH_ + c);
            Qs[row * 64 + c + 0] = v.x; Qs[row * 64 + c + 1] = v.y;
            Qs[row * 64 + c + 2] = v.z; Qs[row * 64 + c + 3] = v.w;
        }
    }
    if (tid < 64) ksumS[tid] = g_ksum[bh * DH_ + tid];
    __syncthreads();

    if (tid < 64) {
        float m = 0.f;
#pragma unroll 8
        for (int d = 0; d < DH_; d++) {
            int dd = (d + tid) & 63;                  // skew: avoid 32-way conflicts
            m += Qs[tid * 64 + dd] * ksumS[dd];
        }
        meanS[tid] = m * (0.125f / 2048.0f);          // scale/S
    }
    __syncthreads();

    float o[4][4] = {};
    const float lam = 1.0507009873554805f;
    const float la  = 1.0507009873554805f * 1.6732632423543772f;

    for (int j0 = 0; j0 < S_; j0 += 64) {
        // load K tile ([j][d], stride 65) and V tile ([j][d], stride 64)
        {
            int r = tid >> 4;
            int c = (tid & 15) * 4;
#pragma unroll
            for (int rr = 0; rr < 4; rr++) {
                int row = r + rr * 16;
                float4 kv = *(const float4*)(kb + (size_t)(j0 + row) * DH_ + c);
                Ks[row * 65 + c + 0] = kv.x; Ks[row * 65 + c + 1] = kv.y;
                Ks[row * 65 + c + 2] = kv.z; Ks[row * 65 + c + 3] = kv.w;
                float4 vv = *(const float4*)(vb + (size_t)(j0 + row) * D_ + c);
                Vs[row * 64 + c + 0] = vv.x; Vs[row * 64 + c + 1] = vv.y;
                Vs[row * 64 + c + 2] = vv.z; Vs[row * 64 + c + 3] = vv.w;
            }
        }
        __syncthreads();

        // GEMM1: sacc[i][j] = sum_d Q[i,d] * K[j,d]
        float sacc[4][4] = {};
#pragma unroll 8
        for (int d = 0; d < DH_; d++) {
            float ar[4], br[4];
#pragma unroll
            for (int i = 0; i < 4; i++) ar[i] = Qs[(ty * 4 + i) * 64 + d];
#pragma unroll
            for (int j = 0; j < 4; j++) br[j] = Ks[(tx * 4 + j) * 65 + d];
#pragma unroll
            for (int i = 0; i < 4; i++)
#pragma unroll
                for (int j = 0; j < 4; j++)
                    sacc[i][j] += ar[i] * br[j];
        }

        // selu(sim*scale - mean) -> P
#pragma unroll
        for (int i = 0; i < 4; i++) {
            float mn = meanS[ty * 4 + i];
#pragma unroll
            for (int j = 0; j < 4; j++) {
                float v = sacc[i][j] * 0.125f - mn;
                float p = (v > 0.f) ? lam * v : la * (__expf(v) - 1.f);
                Ps[(ty * 4 + i) * 65 + tx * 4 + j] = p;
            }
        }
        __syncthreads();

        // GEMM2: o[i][d] += sum_j P[i,j] * V[j,d]
#pragma unroll 8
        for (int j = 0; j < 64; j++) {
            float ar[4];
#pragma unroll
            for (int i = 0; i < 4; i++) ar[i] = Ps[(ty * 4 + i) * 65 + j];  // broadcast
            float4 bv = *(const float4*)&Vs[j * 64 + tx * 4];
            float br[4] = {bv.x, bv.y, bv.z, bv.w};
#pragma unroll
            for (int i = 0; i < 4; i++)
#pragma unroll
                for (int d = 0; d < 4; d++)
                    o[i][d] += ar[i] * br[d];
        }
        __syncthreads();
    }

    // epilogue: out[b, s, h*64 + d], scaled by S^-0.5
    const float invS = 0.02209708691207961f;  // 2048^-0.5
#pragma unroll
    for (int i = 0; i < 4; i++) {
        int s = i0 + ty * 4 + i;
        float* op = out + ((size_t)b * S_ + s) * D_ + h * DH_ + tx * 4;
#pragma unroll
        for (int d = 0; d < 4; d++) op[d] = o[i][d] * invS;
    }
}

// ---------------------------------------------------------------------------
extern "C" void kernel_launch(void* const* d_in, const int* in_sizes, int n_in,
                              void* d_out, int out_size) {
    const float* x = (const float*)d_in[0];
    const float* W = (const float*)d_in[1];
    const float* b = (const float*)d_in[2];
    float* out = (float*)d_out;

    cudaFuncSetAttribute(attn_kernel, cudaFuncAttributeMaxDynamicSharedMemorySize,
                         ATTN_SMEM_BYTES);

    proj_kernel<<<dim3(32, 128), 256>>>(x, W, b);
    ksum_kernel<<<BH_, DH_>>>();
    attn_kernel<<<dim3(S_ / 64, BH_), 256, ATTN_SMEM_BYTES>>>(x, out);
}

// round 7
// speedup vs baseline: 2.1272x; 2.1245x over previous
#include <cuda_runtime.h>
#include <cuda_bf16.h>
#include <cstdint>

#define B_   4
#define S_   2048
#define D_   1024
#define H_   16
#define DH_  64
#define BH_  64

// ---------------------------------------------------------------------------
// Scratch: packed u32 per element = (hi bf16) | (lo bf16 << 16)
// ---------------------------------------------------------------------------
__device__ uint32_t g_q[(size_t)BH_ * S_ * DH_];    // [bh][s][d]
__device__ uint32_t g_k[(size_t)BH_ * S_ * DH_];    // [bh][s][d]
__device__ uint32_t g_vt[(size_t)BH_ * DH_ * S_];   // [bh][d][s]
__device__ float g_ksum[BH_ * DH_];

// ---------------------------------------------------------------------------
// helpers
// ---------------------------------------------------------------------------
__device__ __forceinline__ uint32_t smem_u32(const void* p) {
    uint32_t a;
    asm("{ .reg .u64 t; cvta.to.shared.u64 t, %1; cvt.u32.u64 %0, t; }" : "=r"(a) : "l"(p));
    return a;
}

// fp32 -> packed (hi bf16 | lo bf16 << 16)
__device__ __forceinline__ uint32_t packf(float v) {
    __nv_bfloat16 h = __float2bfloat16_rn(v);
    __nv_bfloat16 l = __float2bfloat16_rn(v - __bfloat162float(h));
    return (uint32_t)(*(uint16_t*)&h) | ((uint32_t)(*(uint16_t*)&l) << 16);
}
__device__ __forceinline__ float unpackf(uint32_t w) {
    uint16_t a = (uint16_t)(w & 0xffff), b = (uint16_t)(w >> 16);
    return __bfloat162float(*(__nv_bfloat16*)&a) + __bfloat162float(*(__nv_bfloat16*)&b);
}
// split two fp32 -> bf16x2 hi-pair and lo-pair (low half = first elem)
__device__ __forceinline__ void split2(float v0, float v1, uint32_t& hi, uint32_t& lo) {
    __nv_bfloat162 hb = __float22bfloat162_rn(make_float2(v0, v1));
    float r0 = v0 - __bfloat162float(hb.x);
    float r1 = v1 - __bfloat162float(hb.y);
    __nv_bfloat162 lb = __float22bfloat162_rn(make_float2(r0, r1));
    hi = *(uint32_t*)&hb;
    lo = *(uint32_t*)&lb;
}

#define LDSM_X4(R0, R1, R2, R3, ADDR) \
    asm volatile("ldmatrix.sync.aligned.m8n8.x4.shared.b16 {%0,%1,%2,%3}, [%4];" \
                 : "=r"(R0), "=r"(R1), "=r"(R2), "=r"(R3) : "r"(ADDR))

#define MMA16816(D, A, B0, B1) \
    asm volatile("mma.sync.aligned.m16n8k16.row.col.f32.bf16.bf16.f32 " \
                 "{%0,%1,%2,%3}, {%4,%5,%6,%7}, {%8,%9}, {%0,%1,%2,%3};" \
                 : "+f"((D)[0]), "+f"((D)[1]), "+f"((D)[2]), "+f"((D)[3]) \
                 : "r"((A)[0]), "r"((A)[1]), "r"((A)[2]), "r"((A)[3]), "r"(B0), "r"(B1))

// ---------------------------------------------------------------------------
// Kernel 1: transpose-convert x -> V^T packed  [bh][d][s]
// ---------------------------------------------------------------------------
__global__ __launch_bounds__(256) void convert_vt_kernel(const float* __restrict__ x) {
    __shared__ float t[64][129];
    int bh = blockIdx.x, s0 = blockIdx.y * 128;
    int b = bh >> 4, h = bh & 15;
    int tid = threadIdx.x;
    const float* xb = x + ((size_t)b * S_ + s0) * D_ + h * DH_;
#pragma unroll
    for (int u = 0; u < 8; u++) {
        int id = u * 256 + tid;
        int r = id >> 4, c4 = id & 15;
        float4 v = *(const float4*)(xb + (size_t)r * D_ + c4 * 4);
        t[c4 * 4 + 0][r] = v.x; t[c4 * 4 + 1][r] = v.y;
        t[c4 * 4 + 2][r] = v.z; t[c4 * 4 + 3][r] = v.w;
    }
    __syncthreads();
    int d = tid >> 2, sc = (tid & 3) * 32;
    uint32_t wb[32];
#pragma unroll
    for (int p = 0; p < 32; p++) wb[p] = packf(t[d][sc + p]);
    uint4* dst = (uint4*)(g_vt + ((size_t)bh * 64 + d) * S_ + s0 + sc);
#pragma unroll
    for (int q = 0; q < 8; q++)
        dst[q] = make_uint4(wb[4 * q], wb[4 * q + 1], wb[4 * q + 2], wb[4 * q + 3]);
}

// ---------------------------------------------------------------------------
// Kernel 2: projection GEMM via mma.sync bf16x3.
// C[m,n] = x[m,:] . W[n,:] + bias[n];  CTA tile 128x128, K-step 32.
// 8 warps: wm = w>>1 (32 rows), wn = w&1 (64 cols).
// ---------------------------------------------------------------------------
__global__ __launch_bounds__(256) void proj_mma_kernel(const float* __restrict__ x,
                                                       const float* __restrict__ W,
                                                       const float* __restrict__ bias) {
    __shared__ uint16_t Ah[128 * 40], Al[128 * 40], Bh[128 * 40], Bl[128 * 40];
    __shared__ float bias_s[128];
    const int tid = threadIdx.x, lane = tid & 31, w = tid >> 5;
    const int wm = w >> 1, wn = w & 1;
    const int n0 = blockIdx.x * 128, m0 = blockIdx.y * 128;
    if (tid < 128) bias_s[tid] = bias[n0 + tid];

    const uint32_t sAh = smem_u32(Ah), sAl = smem_u32(Al);
    const uint32_t sBh = smem_u32(Bh), sBl = smem_u32(Bl);

    const float* Ag = x + (size_t)m0 * D_;
    const float* Bg = W + (size_t)n0 * D_;
    const int lr = tid >> 1, lc = (tid & 1) * 16;

    float acc[2][8][4] = {};
    float4 fa[4], fb[4];
#pragma unroll
    for (int i = 0; i < 4; i++) {
        fa[i] = *(const float4*)(Ag + (size_t)lr * D_ + lc + i * 4);
        fb[i] = *(const float4*)(Bg + (size_t)lr * D_ + lc + i * 4);
    }

    for (int ks = 0; ks < 32; ks++) {
        __syncthreads();   // previous MMAs done
#pragma unroll
        for (int i = 0; i < 4; i++) {
            uint32_t h0, l0, h1, l1;
            int idx = lr * 40 + lc + i * 4;
            split2(fa[i].x, fa[i].y, h0, l0);
            split2(fa[i].z, fa[i].w, h1, l1);
            *(uint32_t*)&Ah[idx] = h0; *(uint32_t*)&Ah[idx + 2] = h1;
            *(uint32_t*)&Al[idx] = l0; *(uint32_t*)&Al[idx + 2] = l1;
            split2(fb[i].x, fb[i].y, h0, l0);
            split2(fb[i].z, fb[i].w, h1, l1);
            *(uint32_t*)&Bh[idx] = h0; *(uint32_t*)&Bh[idx + 2] = h1;
            *(uint32_t*)&Bl[idx] = l0; *(uint32_t*)&Bl[idx + 2] = l1;
        }
        __syncthreads();
        if (ks < 31) {
            int k0 = (ks + 1) * 32;
#pragma unroll
            for (int i = 0; i < 4; i++) {
                fa[i] = *(const float4*)(Ag + (size_t)lr * D_ + k0 + lc + i * 4);
                fb[i] = *(const float4*)(Bg + (size_t)lr * D_ + k0 + lc + i * 4);
            }
        }
#pragma unroll
        for (int kb = 0; kb < 2; kb++) {
            uint32_t ah[2][4], al[2][4];
#pragma unroll
            for (int mf = 0; mf < 2; mf++) {
                int row = wm * 32 + mf * 16 + (lane & 7) + ((lane >> 3) & 1) * 8;
                int unit = kb * 2 + (lane >> 4);
                uint32_t off = (uint32_t)(row * 40 + unit * 8) * 2;
                LDSM_X4(ah[mf][0], ah[mf][1], ah[mf][2], ah[mf][3], sAh + off);
                LDSM_X4(al[mf][0], al[mf][1], al[mf][2], al[mf][3], sAl + off);
            }
#pragma unroll
            for (int nb = 0; nb < 4; nb++) {
                uint32_t bh[4], bl[4];
                int row = wn * 64 + nb * 16 + (lane & 7) + ((lane >> 4) << 3);
                int unit = kb * 2 + ((lane >> 3) & 1);
                uint32_t off = (uint32_t)(row * 40 + unit * 8) * 2;
                LDSM_X4(bh[0], bh[1], bh[2], bh[3], sBh + off);
                LDSM_X4(bl[0], bl[1], bl[2], bl[3], sBl + off);
#pragma unroll
                for (int mf = 0; mf < 2; mf++) {
                    MMA16816(acc[mf][nb * 2],     ah[mf], bh[0], bh[1]);
                    MMA16816(acc[mf][nb * 2 + 1], ah[mf], bh[2], bh[3]);
                    MMA16816(acc[mf][nb * 2],     al[mf], bh[0], bh[1]);
                    MMA16816(acc[mf][nb * 2 + 1], al[mf], bh[2], bh[3]);
                    MMA16816(acc[mf][nb * 2],     ah[mf], bl[0], bl[1]);
                    MMA16816(acc[mf][nb * 2 + 1], ah[mf], bl[2], bl[3]);
                }
            }
        }
    }

    // epilogue: c-frag (row = +lane>>2 / +8, col pair = (lane&3)*2) -> q/k scatter
#pragma unroll
    for (int mf = 0; mf < 2; mf++) {
#pragma unroll
        for (int e2 = 0; e2 < 2; e2++) {
            int row = m0 + wm * 32 + mf * 16 + (lane >> 2) + e2 * 8;
            int bb = row >> 11, ss = row & 2047;
#pragma unroll
            for (int nf = 0; nf < 8; nf++) {
                int cl = wn * 64 + nf * 8 + (lane & 3) * 2;   // local col (even)
                float qv = acc[mf][nf][e2 * 2 + 0] + bias_s[cl];
                float kv = acc[mf][nf][e2 * 2 + 1] + bias_s[cl + 1];
                int hd = (n0 + cl) >> 1;
                int hh = hd >> 6, dd = hd & 63;
                size_t off = ((size_t)((bb << 4) + hh) * S_ + ss) * DH_ + dd;
                g_q[off] = packf(qv);
                g_k[off] = packf(kv);
            }
        }
    }
}

// ---------------------------------------------------------------------------
// Kernel 3: ksum[bh][d] = sum_s k[bh][s][d]
// ---------------------------------------------------------------------------
__global__ __launch_bounds__(512) void ksum_kernel() {
    __shared__ float part[8][64];
    int bh = blockIdx.x;
    int p = threadIdx.x >> 6, d = threadIdx.x & 63;
    const uint32_t* kp = g_k + (size_t)bh * S_ * DH_ + d;
    float acc = 0.f;
    for (int s = p; s < S_; s += 8) acc += unpackf(kp[(size_t)s * DH_]);
    part[p][d] = acc;
    __syncthreads();
    if (threadIdx.x < 64) {
        float t = 0.f;
#pragma unroll
        for (int i = 0; i < 8; i++) t += part[i][threadIdx.x];
        g_ksum[bh * 64 + threadIdx.x] = t;
    }
}

// ---------------------------------------------------------------------------
// Kernel 4: fused attention via mma.sync bf16x3.
// CTA: 128 q-rows, 8 warps x 16 rows, loop over 16 j-tiles of 128.
// smem halves layout (stride-padded for conflict-free ldmatrix):
// ---------------------------------------------------------------------------
#define AT_QH 0
#define AT_QL (128 * 72)
#define AT_KH (2 * 128 * 72)
#define AT_KL (3 * 128 * 72)
#define AT_VH (4 * 128 * 72)
#define AT_VL (4 * 128 * 72 + 64 * 136)
#define AT_HALVES (4 * 128 * 72 + 2 * 64 * 136)
#define ATT_SMEM_BYTES (AT_HALVES * 2 + (64 + 128) * 4)

__global__ __launch_bounds__(256) void attn_mma_kernel(float* __restrict__ out) {
    extern __shared__ uint16_t sh[];
    float* ksum_s = (float*)(sh + AT_HALVES);
    float* mean_s = ksum_s + 64;
    const uint32_t sb = smem_u32(sh);
    const int tid = threadIdx.x, lane = tid & 31, w = tid >> 5;
    const int bh = blockIdx.y, i0 = blockIdx.x * 128;
    const int b = bh >> 4, h = bh & 15;

    // ---- load Q tile (deinterleave packed u32 -> Qh/Ql) ----
    {
        const uint32_t* qg = g_q + ((size_t)bh * S_ + i0) * DH_;
        int lr = tid >> 1, lc = (tid & 1) * 32;
#pragma unroll
        for (int c = 0; c < 8; c++) {
            uint4 v = *(const uint4*)(qg + (size_t)lr * DH_ + lc + c * 4);
            int idx = lr * 72 + lc + c * 4;
            *(uint32_t*)&sh[AT_QH + idx]     = __byte_perm(v.x, v.y, 0x5410);
            *(uint32_t*)&sh[AT_QL + idx]     = __byte_perm(v.x, v.y, 0x7632);
            *(uint32_t*)&sh[AT_QH + idx + 2] = __byte_perm(v.z, v.w, 0x5410);
            *(uint32_t*)&sh[AT_QL + idx + 2] = __byte_perm(v.z, v.w, 0x7632);
        }
    }
    if (tid < 64) ksum_s[tid] = g_ksum[bh * 64 + tid];
    __syncthreads();

    if (tid < 128) {
        float dot = 0.f;
#pragma unroll 16
        for (int d = 0; d < 64; d++) {
            uint16_t hv = sh[AT_QH + tid * 72 + d];
            uint16_t lv = sh[AT_QL + tid * 72 + d];
            float qv = __bfloat162float(*(__nv_bfloat16*)&hv) +
                       __bfloat162float(*(__nv_bfloat16*)&lv);
            dot += qv * ksum_s[d];
        }
        mean_s[tid] = dot * (0.125f / 2048.0f);
    }
    __syncthreads();

    const int rw = w * 16;
    const float mean0 = mean_s[rw + (lane >> 2)];
    const float mean1 = mean_s[rw + (lane >> 2) + 8];
    const float lam = 1.0507009873554805f;
    const float la  = 1.7580993408473766f;   // lambda*alpha

    float o[8][4] = {};
    const uint32_t* kg = g_k + (size_t)bh * S_ * DH_;
    const uint32_t* vg = g_vt + (size_t)bh * DH_ * S_;

    for (int j0 = 0; j0 < S_; j0 += 128) {
        // K tile
        {
            int lr = tid >> 1, lc = (tid & 1) * 32;
#pragma unroll
            for (int c = 0; c < 8; c++) {
                uint4 v = *(const uint4*)(kg + (size_t)(j0 + lr) * DH_ + lc + c * 4);
                int idx = lr * 72 + lc + c * 4;
                *(uint32_t*)&sh[AT_KH + idx]     = __byte_perm(v.x, v.y, 0x5410);
                *(uint32_t*)&sh[AT_KL + idx]     = __byte_perm(v.x, v.y, 0x7632);
                *(uint32_t*)&sh[AT_KH + idx + 2] = __byte_perm(v.z, v.w, 0x5410);
                *(uint32_t*)&sh[AT_KL + idx + 2] = __byte_perm(v.z, v.w, 0x7632);
            }
        }
        // V^T tile [d][j]
        {
            int dr = tid >> 2, qp = (tid & 3) * 32;
#pragma unroll
            for (int c = 0; c < 8; c++) {
                uint4 v = *(const uint4*)(vg + (size_t)dr * S_ + j0 + qp + c * 4);
                int idx = dr * 136 + qp + c * 4;
                *(uint32_t*)&sh[AT_VH + idx]     = __byte_perm(v.x, v.y, 0x5410);
                *(uint32_t*)&sh[AT_VL + idx]     = __byte_perm(v.x, v.y, 0x7632);
                *(uint32_t*)&sh[AT_VH + idx + 2] = __byte_perm(v.z, v.w, 0x5410);
                *(uint32_t*)&sh[AT_VL + idx + 2] = __byte_perm(v.z, v.w, 0x7632);
            }
        }
        __syncthreads();

        // ---- GEMM1: S = Q K^T  (warp: 16 x 128) ----
        float s[16][4] = {};
#pragma unroll
        for (int kb = 0; kb < 4; kb++) {
            uint32_t ah[4], al[4];
            {
                int row = rw + (lane & 7) + ((lane >> 3) & 1) * 8;
                int unit = kb * 2 + (lane >> 4);
                uint32_t off = (uint32_t)(row * 72 + unit * 8) * 2;
                LDSM_X4(ah[0], ah[1], ah[2], ah[3], sb + (AT_QH * 2) + off);
                LDSM_X4(al[0], al[1], al[2], al[3], sb + (AT_QL * 2) + off);
            }
#pragma unroll
            for (int nb = 0; nb < 8; nb++) {
                uint32_t bhv[4], blv[4];
                int row = nb * 16 + (lane & 7) + ((lane >> 4) << 3);
                int unit = kb * 2 + ((lane >> 3) & 1);
                uint32_t off = (uint32_t)(row * 72 + unit * 8) * 2;
                LDSM_X4(bhv[0], bhv[1], bhv[2], bhv[3], sb + (AT_KH * 2) + off);
                LDSM_X4(blv[0], blv[1], blv[2], blv[3], sb + (AT_KL * 2) + off);
                MMA16816(s[nb * 2],     ah, bhv[0], bhv[1]);
                MMA16816(s[nb * 2 + 1], ah, bhv[2], bhv[3]);
                MMA16816(s[nb * 2],     al, bhv[0], bhv[1]);
                MMA16816(s[nb * 2 + 1], al, bhv[2], bhv[3]);
                MMA16816(s[nb * 2],     ah, blv[0], blv[1]);
                MMA16816(s[nb * 2 + 1], ah, blv[2], blv[3]);
            }
        }

        // ---- SELU + split -> P fragments in registers ----
        uint32_t ph[8][4], pl[8][4];
#pragma unroll
        for (int nf = 0; nf < 16; nf++) {
            float v0 = s[nf][0] * 0.125f - mean0;
            float v1 = s[nf][1] * 0.125f - mean0;
            float v2 = s[nf][2] * 0.125f - mean1;
            float v3 = s[nf][3] * 0.125f - mean1;
            float p0 = v0 > 0.f ? lam * v0 : la * (__expf(v0) - 1.f);
            float p1 = v1 > 0.f ? lam * v1 : la * (__expf(v1) - 1.f);
            float p2 = v2 > 0.f ? lam * v2 : la * (__expf(v2) - 1.f);
            float p3 = v3 > 0.f ? lam * v3 : la * (__expf(v3) - 1.f);
            int pb = nf >> 1, base = (nf & 1) * 2;
            split2(p0, p1, ph[pb][base + 0], pl[pb][base + 0]);
            split2(p2, p3, ph[pb][base + 1], pl[pb][base + 1]);
        }

        // ---- GEMM2: O += P V^T  (warp: 16 x 64, K = 128) ----
#pragma unroll
        for (int pb = 0; pb < 8; pb++) {
#pragma unroll
            for (int db = 0; db < 4; db++) {
                uint32_t bhv[4], blv[4];
                int row = db * 16 + (lane & 7) + ((lane >> 4) << 3);
                int unit = pb * 2 + ((lane >> 3) & 1);
                uint32_t off = (uint32_t)(row * 136 + unit * 8) * 2;
                LDSM_X4(bhv[0], bhv[1], bhv[2], bhv[3], sb + (AT_VH * 2) + off);
                LDSM_X4(blv[0], blv[1], blv[2], blv[3], sb + (AT_VL * 2) + off);
                MMA16816(o[db * 2],     ph[pb], bhv[0], bhv[1]);
                MMA16816(o[db * 2 + 1], ph[pb], bhv[2], bhv[3]);
                MMA16816(o[db * 2],     pl[pb], bhv[0], bhv[1]);
                MMA16816(o[db * 2 + 1], pl[pb], bhv[2], bhv[3]);
                MMA16816(o[db * 2],     ph[pb], blv[0], blv[1]);
                MMA16816(o[db * 2 + 1], ph[pb], blv[2], blv[3]);
            }
        }
        __syncthreads();
    }

    // ---- epilogue: out[b][s][h*64+d] = O * S^-0.5 ----
    {
        const float invS = 0.02209708691207961f;
        int row = i0 + rw + (lane >> 2);
        float* op = out + ((size_t)b * S_ + row) * D_ + h * DH_ + (lane & 3) * 2;
#pragma unroll
        for (int nf = 0; nf < 8; nf++) {
            *(float2*)(op + nf * 8) =
                make_float2(o[nf][0] * invS, o[nf][1] * invS);
            *(float2*)(op + 8 * D_ + nf * 8) =
                make_float2(o[nf][2] * invS, o[nf][3] * invS);
        }
    }
}

// ---------------------------------------------------------------------------
extern "C" void kernel_launch(void* const* d_in, const int* in_sizes, int n_in,
                              void* d_out, int out_size) {
    const float* x = (const float*)d_in[0];
    const float* W = (const float*)d_in[1];
    const float* b = (const float*)d_in[2];
    float* out = (float*)d_out;

    cudaFuncSetAttribute(attn_mma_kernel, cudaFuncAttributeMaxDynamicSharedMemorySize,
                         ATT_SMEM_BYTES);

    convert_vt_kernel<<<dim3(BH_, S_ / 128), 256>>>(x);
    proj_mma_kernel<<<dim3(16, 64), 256>>>(x, W, b);
    ksum_kernel<<<BH_, 512>>>();
    attn_mma_kernel<<<dim3(S_ / 128, BH_), 256, ATT_SMEM_BYTES>>>(out);
}